// round 5
// baseline (speedup 1.0000x reference)
#include <cuda_runtime.h>
#include <math_constants.h>

#define N_DEC 16
#define M_LEN 128
#define V_VOC 64
#define H_DIM 128
#define K_TPL 8
#define NP1 17
#define ROWS 136

__device__ __forceinline__ float fmax4(float4 v) {
    return fmaxf(fmaxf(v.x, v.y), fmaxf(v.z, v.w));
}

// One block per batch element. 8 warps = 8 template rows.
// Phase 1: warp k selects sel[k] via argmax over 17 gumbel-perturbed logits.
// Phase 2: warp k scans its selected row for effective length (MLP-8 batched loads).
// Phase 3: offsets known block-wide -> all 8 copies run in parallel; zero tail.
__global__ __launch_bounds__(256, 2)
void fused_kernel(
    const float* __restrict__ decodings,   // [B,16,128,64]
    const float* __restrict__ type_emb,    // [24,128]
    const float* __restrict__ w_sem,       // [15,136,128]
    const float* __restrict__ b_sem,       // [15,136]
    const float* __restrict__ gumbel,      // [B,8,17]
    const int*   __restrict__ target_types,// [B]
    const int*   __restrict__ spans,       // [B]
    float*       __restrict__ out)         // [B,128,64]
{
    const int b    = blockIdx.x;
    const int tid  = threadIdx.x;
    const int lane = tid & 31;
    const int k    = tid >> 5;

    __shared__ float s_emb[H_DIM];
    __shared__ int   s_sel[K_TPL];
    __shared__ int   s_len[K_TPL];

    const int t = target_types[b];

    // ---------------- Phase 1: template selection ----------------
    if (t == 20) {
        if (tid < K_TPL) s_sel[tid] = (tid == 0) ? 1 : 0;
        __syncthreads();
    } else {
        if (tid < H_DIM) s_emb[tid] = type_emb[t * H_DIM + tid];
        __syncthreads();

        const int ti = t - 9;
        const int span = spans[b];
        const float4* __restrict__ w4 = (const float4*)
            (w_sem + ((size_t)ti * ROWS + k * NP1) * H_DIM);     // rows k*17..k*17+16
        const float4 e = ((const float4*)s_emb)[lane];

        // per-lane preload of bias+gumbel for n = lane (lanes 0..16)
        float add = 0.f;
        if (lane < NP1)
            add = b_sem[(size_t)ti * ROWS + k * NP1 + lane]
                + gumbel[((size_t)b * K_TPL + k) * NP1 + lane];

        float best = -CUDART_INF_F;
        int   bestn = 0;
        #pragma unroll 1
        for (int n = 0; n < NP1; n++) {
            float4 wv = w4[n * 32 + lane];
            float acc = wv.x * e.x + wv.y * e.y + wv.z * e.z + wv.w * e.w;
            #pragma unroll
            for (int o = 16; o; o >>= 1)
                acc += __shfl_xor_sync(0xffffffffu, acc, o);
            float val = acc + __shfl_sync(0xffffffffu, add, n);  // all lanes agree
            if (n <= span && val > best) { best = val; bestn = n; }
        }
        if (lane == 0) s_sel[k] = bestn;
        __syncthreads();
    }

    // ---------------- Phase 2: length scan (batched MLP-8 loads) ----------------
    const float* __restrict__ dec = decodings + (size_t)b * N_DEC * M_LEN * V_VOC;
    const int sel = s_sel[k];
    int lenmax = 0;
    if (sel > 0) {
        const float4* __restrict__ row4 = (const float4*)
            (dec + (size_t)(sel - 1) * (M_LEN * V_VOC));
        const int half = lane & 1;       // which 8-float4 half of the position
        const int mloc = lane >> 1;      // 16 positions per super-iteration
        const float4* __restrict__ base = row4 + (half << 3);
        #pragma unroll 1
        for (int iter = 0; iter < 8; iter++) {
            const int m = iter * 16 + mloc;
            const float4* p = base + m * 16;
            float4 x0 = p[0], x1 = p[1], x2 = p[2], x3 = p[3];
            float4 x4 = p[4], x5 = p[5], x6 = p[6], x7 = p[7];
            float cm = fmaxf(fmaxf(fmax4(x1), fmax4(x2)), fmaxf(fmax4(x3), fmax4(x4)));
            cm = fmaxf(cm, fmaxf(fmax4(x5), fmaxf(fmax4(x6), fmax4(x7))));
            float d0 = 0.f;
            if (half == 0) {                       // x0.x is d[m,0]: exclude it
                d0 = x0.x;
                cm = fmaxf(cm, fmaxf(fmaxf(x0.y, x0.z), x0.w));
            } else {
                cm = fmaxf(cm, fmax4(x0));
            }
            float cmp = fmaxf(cm, __shfl_xor_sync(0xffffffffu, cm, 1));
            float d0b = __shfl_sync(0xffffffffu, d0, lane & 0x1e);
            if (cmp > d0b) lenmax = max(lenmax, m + 1);   // token 0 wins ties
        }
        #pragma unroll
        for (int o = 16; o; o >>= 1)
            lenmax = max(lenmax, __shfl_xor_sync(0xffffffffu, lenmax, o));
    }
    if (lane == 0) s_len[k] = lenmax;
    __syncthreads();

    // ---------------- Phase 3: offsets + parallel packed copy ----------------
    int off = 0, eff = 0, cur = 0;
    #pragma unroll
    for (int kk = 0; kk < K_TPL; kk++) {
        const int e = min(s_len[kk], M_LEN - cur);
        if (kk == k) { off = cur; eff = e; }
        cur += e;
    }
    const int tot = cur;   // total packed length (same for all threads)

    float* __restrict__ outb = out + (size_t)b * M_LEN * V_VOC;

    if (eff > 0) {         // warp k copies its row's prefix (hits L1/L2: just read)
        const float4* __restrict__ s4 = (const float4*)
            (dec + (size_t)(sel - 1) * (M_LEN * V_VOC));
        float4* __restrict__ d4 = (float4*)outb + off * 16;
        const int n4 = eff * 16;
        #pragma unroll 4
        for (int i = lane; i < n4; i += 32)
            d4[i] = s4[i];
    }

    // zero tail (distinct addresses; no extra sync needed)
    float4* __restrict__ o4 = (float4*)outb;
    for (int i = tot * 16 + tid; i < M_LEN * 16; i += 256)
        o4[i] = make_float4(0.f, 0.f, 0.f, 0.f);
}

extern "C" void kernel_launch(void* const* d_in, const int* in_sizes, int n_in,
                              void* d_out, int out_size)
{
    const float* decodings    = (const float*)d_in[0];
    const float* type_emb     = (const float*)d_in[1];
    const float* w_sem        = (const float*)d_in[2];
    const float* b_sem        = (const float*)d_in[3];
    const float* gumbel       = (const float*)d_in[4];
    const int*   target_types = (const int*)  d_in[5];
    const int*   spans        = (const int*)  d_in[6];
    float*       out          = (float*)d_out;

    const int B = in_sizes[5];

    fused_kernel<<<B, 256>>>(decodings, type_emb, w_sem, b_sem,
                             gumbel, target_types, spans, out);
}

// round 6
// speedup vs baseline: 1.8190x; 1.8190x over previous
#include <cuda_runtime.h>
#include <math_constants.h>

#define N_DEC 16
#define M_LEN 128
#define V_VOC 64
#define H_DIM 128
#define K_TPL 8
#define NP1 17
#define ROWS 136
#define MAXB 4096

// scratch between kernels
__device__ int g_src[MAXB * K_TPL];
__device__ int g_eff[MAXB * K_TPL];
__device__ int g_off[MAXB * K_TPL];
__device__ int g_tot[MAXB];

__device__ __forceinline__ float fmax4(float4 v) {
    return fmaxf(fmaxf(v.x, v.y), fmaxf(v.z, v.w));
}

// ---------------- Kernel 1: selection + BACKWARD early-exit length scan ----------------
__global__ __launch_bounds__(256, 8)
void select_len_kernel(
    const float* __restrict__ decodings,   // [B,16,128,64]
    const float* __restrict__ type_emb,    // [24,128]
    const float* __restrict__ w_sem,       // [15,136,128]
    const float* __restrict__ b_sem,       // [15,136]
    const float* __restrict__ gumbel,      // [B,8,17]
    const int*   __restrict__ target_types,// [B]
    const int*   __restrict__ spans)       // [B]
{
    const int b    = blockIdx.x;
    const int tid  = threadIdx.x;
    const int lane = tid & 31;
    const int k    = tid >> 5;             // warp = template row

    __shared__ float s_emb[H_DIM];
    __shared__ int   s_sel[K_TPL];
    __shared__ int   s_len[K_TPL];

    const int t = target_types[b];

    // ---- Phase 1: selection ----
    if (t == 20) {
        if (tid < K_TPL) s_sel[tid] = (tid == 0) ? 1 : 0;
        __syncthreads();
    } else {
        if (tid < H_DIM) s_emb[tid] = type_emb[t * H_DIM + tid];
        __syncthreads();

        const int ti = t - 9;
        const int span = spans[b];
        const float4* __restrict__ w4 = (const float4*)
            (w_sem + ((size_t)ti * ROWS + k * NP1) * H_DIM);
        const float4 e = ((const float4*)s_emb)[lane];

        float add = 0.f;
        if (lane < NP1)
            add = b_sem[(size_t)ti * ROWS + k * NP1 + lane]
                + gumbel[((size_t)b * K_TPL + k) * NP1 + lane];

        float best = -CUDART_INF_F;
        int   bestn = 0;
        #pragma unroll 1
        for (int n = 0; n < NP1; n++) {
            float4 wv = w4[n * 32 + lane];
            float acc = wv.x * e.x + wv.y * e.y + wv.z * e.z + wv.w * e.w;
            #pragma unroll
            for (int o = 16; o; o >>= 1)
                acc += __shfl_xor_sync(0xffffffffu, acc, o);
            float val = acc + __shfl_sync(0xffffffffu, add, n);
            if (n <= span && val > best) { best = val; bestn = n; }
        }
        if (lane == 0) s_sel[k] = bestn;
        __syncthreads();
    }

    // ---- Phase 2: backward scan with early exit ----
    // len = 1 + last m where max_{v>0} d[m,v] > d[m,0]  (token 0 wins ties)
    const int sel = s_sel[k];
    int len = 0;
    if (sel > 0) {
        const float4* __restrict__ row4 = (const float4*)
            (decodings + ((size_t)b * N_DEC + (sel - 1)) * (M_LEN * V_VOC));
        const int half = lane & 1;       // which 8-float4 half of the position
        const int mloc = lane >> 1;      // 16 positions per chunk

        #pragma unroll 1
        for (int c = 7; c >= 0; c--) {
            const int m = c * 16 + mloc;
            const float4* p = row4 + m * 16 + (half << 3);
            float4 x0 = p[0], x1 = p[1], x2 = p[2], x3 = p[3];
            float4 x4 = p[4], x5 = p[5], x6 = p[6], x7 = p[7];
            float cm = fmaxf(fmaxf(fmax4(x1), fmax4(x2)), fmaxf(fmax4(x3), fmax4(x4)));
            cm = fmaxf(cm, fmaxf(fmax4(x5), fmaxf(fmax4(x6), fmax4(x7))));
            float d0 = -CUDART_INF_F;
            if (half == 0) {             // x0.x is d[m,0]: exclude from max
                d0 = x0.x;
                cm = fmaxf(cm, fmaxf(fmaxf(x0.y, x0.z), x0.w));
            } else {
                cm = fmaxf(cm, fmax4(x0));
            }
            float cmp = fmaxf(cm, __shfl_xor_sync(0xffffffffu, cm, 1));
            float d0b = __shfl_sync(0xffffffffu, d0, lane & 0x1e);
            unsigned bal = __ballot_sync(0xffffffffu, cmp > d0b);
            if (bal) {                   // warp-uniform: bal identical across lanes
                int hb = 31 - __clz(bal);
                len = c * 16 + (hb >> 1) + 1;
                break;
            }
        }
    }
    if (lane == 0) s_len[k] = len;
    __syncthreads();

    // ---- offsets: tiny serial scan by thread 0 ----
    if (tid == 0) {
        int cur = 0;
        #pragma unroll
        for (int kk = 0; kk < K_TPL; kk++) {
            const int s   = s_sel[kk];
            const int eff = min(s_len[kk], M_LEN - cur);
            g_src[b * K_TPL + kk] = (s > 0) ? (b * N_DEC + s - 1) : -1;
            g_eff[b * K_TPL + kk] = eff;
            g_off[b * K_TPL + kk] = cur;
            cur += eff;
        }
        g_tot[b] = cur;
    }
}

// ---------------- Kernel 2: fully parallel packed copy + tail zero ----------------
__global__ __launch_bounds__(256, 8)
void pack_copy_kernel(
    const float* __restrict__ decodings,   // [B,16,128,64]
    float*       __restrict__ out)         // [B,128,64]
{
    const int b   = blockIdx.x;
    const int k   = blockIdx.y;            // 0..7 copy, 8 = tail zero
    const int tid = threadIdx.x;

    float* __restrict__ outb = out + (size_t)b * M_LEN * V_VOC;

    if (k == K_TPL) {
        const int tot = g_tot[b];
        float4* __restrict__ o4 = (float4*)outb;
        for (int i = tot * 16 + tid; i < M_LEN * 16; i += 256)
            o4[i] = make_float4(0.f, 0.f, 0.f, 0.f);
        return;
    }

    const int eff = g_eff[b * K_TPL + k];
    if (eff == 0) return;
    const int src = g_src[b * K_TPL + k];
    const int off = g_off[b * K_TPL + k];

    const float4* __restrict__ s4 = (const float4*)
        (decodings + (size_t)src * (M_LEN * V_VOC));
    float4* __restrict__ d4 = (float4*)(outb + off * V_VOC);

    const int n4 = eff * 16;
    #pragma unroll 4
    for (int i = tid; i < n4; i += 256)
        d4[i] = s4[i];
}

extern "C" void kernel_launch(void* const* d_in, const int* in_sizes, int n_in,
                              void* d_out, int out_size)
{
    const float* decodings    = (const float*)d_in[0];
    const float* type_emb     = (const float*)d_in[1];
    const float* w_sem        = (const float*)d_in[2];
    const float* b_sem        = (const float*)d_in[3];
    const float* gumbel       = (const float*)d_in[4];
    const int*   target_types = (const int*)  d_in[5];
    const int*   spans        = (const int*)  d_in[6];
    float*       out          = (float*)d_out;

    const int B = in_sizes[5];

    select_len_kernel<<<B, 256>>>(decodings, type_emb, w_sem, b_sem,
                                  gumbel, target_types, spans);
    dim3 grid2(B, K_TPL + 1);
    pack_copy_kernel<<<grid2, 256>>>(decodings, out);
}

// round 7
// speedup vs baseline: 2.3780x; 1.3073x over previous
#include <cuda_runtime.h>
#include <math_constants.h>

#define N_DEC 16
#define M_LEN 128
#define V_VOC 64
#define H_DIM 128
#define K_TPL 8
#define NP1 17
#define ROWS 136
#define MAXB 4096

// scratch between kernels
__device__ int g_src[MAXB * K_TPL];   // decodings row (b*16 + sel-1), or -1
__device__ int g_eff[MAXB * K_TPL];
__device__ int g_off[MAXB * K_TPL];

__device__ __forceinline__ float fmax4(float4 v) {
    return fmaxf(fmaxf(v.x, v.y), fmaxf(v.z, v.w));
}

// ---------------- Kernel 1: selection (high-ILP GEMV) + backward early-exit scan ----------------
__global__ __launch_bounds__(256, 2)
void select_len_kernel(
    const float* __restrict__ decodings,   // [B,16,128,64]
    const float* __restrict__ type_emb,    // [24,128]
    const float* __restrict__ w_sem,       // [15,136,128]
    const float* __restrict__ b_sem,       // [15,136]
    const float* __restrict__ gumbel,      // [B,8,17]
    const int*   __restrict__ target_types,// [B]
    const int*   __restrict__ spans)       // [B]
{
    const int b    = blockIdx.x;
    const int tid  = threadIdx.x;
    const int lane = tid & 31;
    const int k    = tid >> 5;             // warp = template row

    __shared__ float s_emb[H_DIM];
    __shared__ int   s_sel[K_TPL];
    __shared__ int   s_len[K_TPL];

    const int t = target_types[b];

    // ---- Phase 1: selection ----
    if (t == 20) {
        if (tid < K_TPL) s_sel[tid] = (tid == 0) ? 1 : 0;
        __syncthreads();
    } else {
        if (tid < H_DIM) s_emb[tid] = type_emb[t * H_DIM + tid];
        __syncthreads();

        const int ti = t - 9;
        const int span = spans[b];
        const float4* __restrict__ w4 = (const float4*)
            (w_sem + ((size_t)ti * ROWS + k * NP1) * H_DIM);
        const float4 e = ((const float4*)s_emb)[lane];

        // bias + gumbel for n = lane (lanes 0..16)
        float add = 0.f;
        if (lane < NP1)
            add = b_sem[(size_t)ti * ROWS + k * NP1 + lane]
                + gumbel[((size_t)b * K_TPL + k) * NP1 + lane];

        // stage 1: 17 independent partial dots (4 elems per lane each)
        float p[NP1];
        #pragma unroll
        for (int n = 0; n < NP1; n++) {
            float4 wv = w4[n * 32 + lane];
            p[n] = wv.x * e.x + wv.y * e.y + wv.z * e.z + wv.w * e.w;
        }
        // stage 2: batched butterfly — 17-wide ILP between dependent levels
        #pragma unroll
        for (int o = 16; o; o >>= 1) {
            #pragma unroll
            for (int n = 0; n < NP1; n++)
                p[n] += __shfl_xor_sync(0xffffffffu, p[n], o);
        }
        // stage 3: all lanes hold identical sums; statically-unrolled argmax
        float best = -CUDART_INF_F;
        int   bestn = 0;
        #pragma unroll
        for (int n = 0; n < NP1; n++) {
            float val = p[n] + __shfl_sync(0xffffffffu, add, n);
            if (n <= span && val > best) { best = val; bestn = n; }  // first-max tiebreak
        }
        if (lane == 0) s_sel[k] = bestn;
        __syncthreads();
    }

    // ---- Phase 2: backward scan with early exit ----
    const int sel = s_sel[k];
    int len = 0;
    if (sel > 0) {
        const float4* __restrict__ row4 = (const float4*)
            (decodings + ((size_t)b * N_DEC + (sel - 1)) * (M_LEN * V_VOC));
        const int half = lane & 1;
        const int mloc = lane >> 1;

        #pragma unroll 1
        for (int c = 7; c >= 0; c--) {
            const int m = c * 16 + mloc;
            const float4* p4 = row4 + m * 16 + (half << 3);
            float4 x0 = p4[0], x1 = p4[1], x2 = p4[2], x3 = p4[3];
            float4 x4 = p4[4], x5 = p4[5], x6 = p4[6], x7 = p4[7];
            float cm = fmaxf(fmaxf(fmax4(x1), fmax4(x2)), fmaxf(fmax4(x3), fmax4(x4)));
            cm = fmaxf(cm, fmaxf(fmax4(x5), fmaxf(fmax4(x6), fmax4(x7))));
            float d0 = -CUDART_INF_F;
            if (half == 0) {             // x0.x is d[m,0]: exclude from candidate max
                d0 = x0.x;
                cm = fmaxf(cm, fmaxf(fmaxf(x0.y, x0.z), x0.w));
            } else {
                cm = fmaxf(cm, fmax4(x0));
            }
            float cmp = fmaxf(cm, __shfl_xor_sync(0xffffffffu, cm, 1));
            float d0b = __shfl_sync(0xffffffffu, d0, lane & 0x1e);
            unsigned bal = __ballot_sync(0xffffffffu, cmp > d0b);
            if (bal) {                   // warp-uniform
                int hb = 31 - __clz(bal);
                len = c * 16 + (hb >> 1) + 1;
                break;
            }
        }
    }
    if (lane == 0) s_len[k] = len;
    __syncthreads();

    if (tid == 0) {
        int cur = 0;
        #pragma unroll
        for (int kk = 0; kk < K_TPL; kk++) {
            const int s   = s_sel[kk];
            const int eff = min(s_len[kk], M_LEN - cur);
            g_src[b * K_TPL + kk] = (s > 0) ? (b * N_DEC + s - 1) : -1;
            g_eff[b * K_TPL + kk] = eff;
            g_off[b * K_TPL + kk] = cur;
            cur += eff;
        }
    }
}

// ---------------- Kernel 2: gather-style packed copy (no idle blocks) ----------------
__global__ __launch_bounds__(256, 8)
void pack_gather_kernel(
    const float* __restrict__ decodings,   // [B,16,128,64]
    float*       __restrict__ out)         // [B,128,64]
{
    const int b   = blockIdx.x;
    const int tid = threadIdx.x;

    __shared__ int s_off[K_TPL], s_eff[K_TPL], s_src[K_TPL];
    if (tid < K_TPL) {
        s_off[tid] = g_off[b * K_TPL + tid];
        s_eff[tid] = g_eff[b * K_TPL + tid];
        s_src[tid] = g_src[b * K_TPL + tid];
    }
    __syncthreads();

    const float4* __restrict__ dec4 = (const float4*)decodings;
    float4* __restrict__ out4 = (float4*)out + (size_t)b * (M_LEN * 16);

    #pragma unroll
    for (int j = 0; j < 8; j++) {
        const int i = tid + j * 256;      // float4 index in [0, 2048)
        const int m = i >> 4;             // output position
        const int c = i & 15;             // float4 within position
        int srow = -1, sp = 0;
        #pragma unroll
        for (int kk = 0; kk < K_TPL; kk++) {
            const int o = s_off[kk];
            if (m >= o && m < o + s_eff[kk]) { srow = s_src[kk]; sp = m - o; }
        }
        float4 v = make_float4(0.f, 0.f, 0.f, 0.f);
        if (srow >= 0)
            v = dec4[(size_t)srow * (M_LEN * 16) + sp * 16 + c];
        out4[i] = v;
    }
}

extern "C" void kernel_launch(void* const* d_in, const int* in_sizes, int n_in,
                              void* d_out, int out_size)
{
    const float* decodings    = (const float*)d_in[0];
    const float* type_emb     = (const float*)d_in[1];
    const float* w_sem        = (const float*)d_in[2];
    const float* b_sem        = (const float*)d_in[3];
    const float* gumbel       = (const float*)d_in[4];
    const int*   target_types = (const int*)  d_in[5];
    const int*   spans        = (const int*)  d_in[6];
    float*       out          = (float*)d_out;

    const int B = in_sizes[5];

    select_len_kernel<<<B, 256>>>(decodings, type_emb, w_sem, b_sem,
                                  gumbel, target_types, spans);
    pack_gather_kernel<<<B, 256>>>(decodings, out);
}

// round 8
// speedup vs baseline: 2.4436x; 1.0276x over previous
#include <cuda_runtime.h>
#include <math_constants.h>

#define N_DEC 16
#define M_LEN 128
#define V_VOC 64
#define H_DIM 128
#define K_TPL 8
#define NP1 17
#define ROWS 136
#define MAXB 4096

// scratch between kernels
__device__ int g_src[MAXB * K_TPL];   // decodings row (b*16 + sel-1), or -1
__device__ int g_eff[MAXB * K_TPL];
__device__ int g_off[MAXB * K_TPL];

__device__ __forceinline__ float fmax4(float4 v) {
    return fmaxf(fmaxf(v.x, v.y), fmaxf(v.z, v.w));
}

// ---------------- Kernel 1: selection (high-ILP GEMV) + backward early-exit scan ----------------
__global__ __launch_bounds__(256, 2)
void select_len_kernel(
    const float* __restrict__ decodings,   // [B,16,128,64]
    const float* __restrict__ type_emb,    // [24,128]
    const float* __restrict__ w_sem,       // [15,136,128]
    const float* __restrict__ b_sem,       // [15,136]
    const float* __restrict__ gumbel,      // [B,8,17]
    const int*   __restrict__ target_types,// [B]
    const int*   __restrict__ spans)       // [B]
{
    const int b    = blockIdx.x;
    const int tid  = threadIdx.x;
    const int lane = tid & 31;
    const int k    = tid >> 5;             // warp = template row

    __shared__ float s_emb[H_DIM];
    __shared__ int   s_sel[K_TPL];
    __shared__ int   s_len[K_TPL];

    const int t = target_types[b];

    // ---- Phase 1: selection ----
    if (t == 20) {
        if (tid < K_TPL) s_sel[tid] = (tid == 0) ? 1 : 0;
        __syncthreads();
    } else {
        if (tid < H_DIM) s_emb[tid] = type_emb[t * H_DIM + tid];
        __syncthreads();

        const int ti = t - 9;
        const int span = spans[b];
        const float4* __restrict__ w4 = (const float4*)
            (w_sem + ((size_t)ti * ROWS + k * NP1) * H_DIM);
        const float4 e = ((const float4*)s_emb)[lane];

        // bias + gumbel for n = lane (lanes 0..16)
        float add = 0.f;
        if (lane < NP1)
            add = b_sem[(size_t)ti * ROWS + k * NP1 + lane]
                + gumbel[((size_t)b * K_TPL + k) * NP1 + lane];

        // 17 independent partial dots, then batched butterfly (17-wide ILP)
        float p[NP1];
        #pragma unroll
        for (int n = 0; n < NP1; n++) {
            float4 wv = w4[n * 32 + lane];
            p[n] = wv.x * e.x + wv.y * e.y + wv.z * e.z + wv.w * e.w;
        }
        #pragma unroll
        for (int o = 16; o; o >>= 1) {
            #pragma unroll
            for (int n = 0; n < NP1; n++)
                p[n] += __shfl_xor_sync(0xffffffffu, p[n], o);
        }
        float best = -CUDART_INF_F;
        int   bestn = 0;
        #pragma unroll
        for (int n = 0; n < NP1; n++) {
            float val = p[n] + __shfl_sync(0xffffffffu, add, n);
            if (n <= span && val > best) { best = val; bestn = n; }  // first-max
        }
        if (lane == 0) s_sel[k] = bestn;
        __syncthreads();
    }

    // ---- Phase 2: backward scan with early exit (chunk 7 hits w.p. ~1) ----
    const int sel = s_sel[k];
    int len = 0;
    if (sel > 0) {
        const float4* __restrict__ row4 = (const float4*)
            (decodings + ((size_t)b * N_DEC + (sel - 1)) * (M_LEN * V_VOC));
        const int half = lane & 1;
        const int mloc = lane >> 1;

        #pragma unroll 1
        for (int c = 7; c >= 0; c--) {
            const int m = c * 16 + mloc;
            const float4* p4 = row4 + m * 16 + (half << 3);
            float4 x0 = p4[0], x1 = p4[1], x2 = p4[2], x3 = p4[3];
            float4 x4 = p4[4], x5 = p4[5], x6 = p4[6], x7 = p4[7];
            float cm = fmaxf(fmaxf(fmax4(x1), fmax4(x2)), fmaxf(fmax4(x3), fmax4(x4)));
            cm = fmaxf(cm, fmaxf(fmax4(x5), fmaxf(fmax4(x6), fmax4(x7))));
            float d0 = -CUDART_INF_F;
            if (half == 0) {             // x0.x is d[m,0]: exclude from candidate max
                d0 = x0.x;
                cm = fmaxf(cm, fmaxf(fmaxf(x0.y, x0.z), x0.w));
            } else {
                cm = fmaxf(cm, fmax4(x0));
            }
            float cmp = fmaxf(cm, __shfl_xor_sync(0xffffffffu, cm, 1));
            float d0b = __shfl_sync(0xffffffffu, d0, lane & 0x1e);
            unsigned bal = __ballot_sync(0xffffffffu, cmp > d0b);
            if (bal) {                   // warp-uniform
                int hb = 31 - __clz(bal);
                len = c * 16 + (hb >> 1) + 1;
                break;
            }
        }
    }
    if (lane == 0) s_len[k] = len;
    __syncthreads();

    if (tid == 0) {
        int cur = 0;
        #pragma unroll
        for (int kk = 0; kk < K_TPL; kk++) {
            const int s   = s_sel[kk];
            const int eff = min(s_len[kk], M_LEN - cur);
            g_src[b * K_TPL + kk] = (s > 0) ? (b * N_DEC + s - 1) : -1;
            g_eff[b * K_TPL + kk] = eff;
            g_off[b * K_TPL + kk] = cur;
            cur += eff;
        }
    }
}

// ---------------- Kernel 2: gather-style packed copy, 4 blocks per batch elem ----------------
__global__ __launch_bounds__(256, 8)
void pack_gather_kernel(
    const float* __restrict__ decodings,   // [B,16,128,64]
    float*       __restrict__ out)         // [B,128,64]
{
    const int b    = blockIdx.x;
    const int part = blockIdx.y;           // 0..3: 32 output positions each
    const int tid  = threadIdx.x;

    __shared__ int s_off[K_TPL], s_eff[K_TPL], s_src[K_TPL];
    if (tid < K_TPL) {
        s_off[tid] = g_off[b * K_TPL + tid];
        s_eff[tid] = g_eff[b * K_TPL + tid];
        s_src[tid] = g_src[b * K_TPL + tid];
    }
    __syncthreads();

    const float4* __restrict__ dec4 = (const float4*)decodings;
    float4* __restrict__ out4 = (float4*)out + (size_t)b * (M_LEN * 16) + part * 512;

    #pragma unroll
    for (int j = 0; j < 2; j++) {
        const int i = tid + j * 256;         // local float4 index in [0, 512)
        const int m = (part * 512 + i) >> 4; // output position
        const int c = i & 15;                // float4 within position
        int srow = -1, sp = 0;
        #pragma unroll
        for (int kk = 0; kk < K_TPL; kk++) {
            const int o = s_off[kk];
            if (m >= o && m < o + s_eff[kk]) { srow = s_src[kk]; sp = m - o; }
        }
        float4 v = make_float4(0.f, 0.f, 0.f, 0.f);
        if (srow >= 0)
            v = dec4[(size_t)srow * (M_LEN * 16) + sp * 16 + c];
        out4[i] = v;
    }
}

extern "C" void kernel_launch(void* const* d_in, const int* in_sizes, int n_in,
                              void* d_out, int out_size)
{
    const float* decodings    = (const float*)d_in[0];
    const float* type_emb     = (const float*)d_in[1];
    const float* w_sem        = (const float*)d_in[2];
    const float* b_sem        = (const float*)d_in[3];
    const float* gumbel       = (const float*)d_in[4];
    const int*   target_types = (const int*)  d_in[5];
    const int*   spans        = (const int*)  d_in[6];
    float*       out          = (float*)d_out;

    const int B = in_sizes[5];

    select_len_kernel<<<B, 256>>>(decodings, type_emb, w_sem, b_sem,
                                  gumbel, target_types, spans);
    dim3 grid2(B, 4);
    pack_gather_kernel<<<grid2, 256>>>(decodings, out);
}